// round 9
// baseline (speedup 1.0000x reference)
#include <cuda_runtime.h>
#include <math.h>

#define NS 1024
#define NR 4096
#define GRID 148                      // one wave, one block per SM
#define TPB 1024                      // thread t owns residues 4t..4t+3
#define F4S (NR * 3 / 4)              // 3072 float4 per sample

// ---------------- scratch (static device globals; no allocation) ----------------
__device__ __align__(16) float4 g_wt4[NR];   // (w*t_c0, w*t_c1, w*t_c2, w)
__device__ float g_stats[8];                 // [4]=1/Lt, [5]=1/d0^2
__device__ float g_S[NS * 12];               // per sample: S(9), P(3)
__device__ float g_RT[NS * 14];              // per sample: R(9), c(3), invd0, invLt

__device__ __forceinline__ float warpsum(float v) {
#pragma unroll
    for (int o = 16; o; o >>= 1) v += __shfl_down_sync(0xffffffffu, v, o);
    return v;
}

__device__ __forceinline__ float rcp_fast(float x) {
    float r;
    asm("rcp.approx.f32 %0, %1;" : "=f"(r) : "f"(x));
    return r;
}

// ---------------- kernel A: true stats + wt4 companion ----------------
#define PRE_T 1024
__global__ void k_pre(const float* __restrict__ truec, const int* __restrict__ mask) {
    int tid = threadIdx.x;
    float ws = 0.f, wt0 = 0.f, wt1 = 0.f, wt2 = 0.f;
    for (int l = tid; l < NR; l += PRE_T) {
        float w = (mask[l] != 0) ? 1.0f : 0.0f;
        ws += w;
        wt0 += w * truec[l * 3 + 0];
        wt1 += w * truec[l * 3 + 1];
        wt2 += w * truec[l * 3 + 2];
    }
    __shared__ float sm[4][32];
    __shared__ float s_tm[3];
    int lane = tid & 31, wid = tid >> 5;
    ws = warpsum(ws); wt0 = warpsum(wt0); wt1 = warpsum(wt1); wt2 = warpsum(wt2);
    if (lane == 0) { sm[0][wid] = ws; sm[1][wid] = wt0; sm[2][wid] = wt1; sm[3][wid] = wt2; }
    __syncthreads();
    if (tid == 0) {
        float Lt = 0.f, a = 0.f, b = 0.f, c = 0.f;
        for (int i = 0; i < 32; i++) { Lt += sm[0][i]; a += sm[1][i]; b += sm[2][i]; c += sm[3][i]; }
        float inv = 1.0f / Lt;
        float m0 = a * inv, m1 = b * inv, m2 = c * inv;
        float d0 = (Lt <= 15.0f) ? 0.5f : (1.24f * cbrtf(Lt - 15.0f) - 1.8f);
        d0 = fmaxf(d0, 0.5f);
        g_stats[0] = m0; g_stats[1] = m1; g_stats[2] = m2;
        g_stats[3] = Lt; g_stats[4] = inv; g_stats[5] = 1.0f / (d0 * d0);
        s_tm[0] = m0; s_tm[1] = m1; s_tm[2] = m2;
    }
    __syncthreads();
    float m0 = s_tm[0], m1 = s_tm[1], m2 = s_tm[2];
    for (int l = tid; l < NR; l += PRE_T) {
        float w = (mask[l] != 0) ? 1.0f : 0.0f;
        float4 v;
        v.x = w * (truec[l * 3 + 0] - m0);
        v.y = w * (truec[l * 3 + 1] - m1);
        v.z = w * (truec[l * 3 + 2] - m2);
        v.w = w;
        g_wt4[l] = v;
    }
}

// ---------------- kernel B: covariance, multi-sample persistent blocks ----------------
#define RES_ACC(wv, px, py, pz, tx, ty, tz) do { \
    S00 = fmaf((px), (tx), S00); S01 = fmaf((px), (ty), S01); S02 = fmaf((px), (tz), S02); \
    S10 = fmaf((py), (tx), S10); S11 = fmaf((py), (ty), S11); S12 = fmaf((py), (tz), S12); \
    S20 = fmaf((pz), (tx), S20); S21 = fmaf((pz), (ty), S21); S22 = fmaf((pz), (tz), S22); \
    P0 = fmaf((wv), (px), P0); P1 = fmaf((wv), (py), P1); P2 = fmaf((wv), (pz), P2); } while (0)

__global__ void __launch_bounds__(TPB, 1) k_cov(const float* __restrict__ pred) {
    int b = blockIdx.x;
    int tid = threadIdx.x;
    int lane = tid & 31, wid = tid >> 5;
    int s0 = (b * NS) / GRID, s1 = ((b + 1) * NS) / GRID;

    __shared__ float red[12][32];

    // companions: loaded once, reused for every sample this block touches
    float4 w0 = g_wt4[4 * tid + 0];
    float4 w1 = g_wt4[4 * tid + 1];
    float4 w2 = g_wt4[4 * tid + 2];
    float4 w3 = g_wt4[4 * tid + 3];

    const float4* __restrict__ base = reinterpret_cast<const float4*>(pred);
    const float4* p4 = base + (size_t)s0 * F4S;
    float4 a = p4[3 * tid + 0];
    float4 bq = p4[3 * tid + 1];
    float4 c = p4[3 * tid + 2];

    for (int s = s0; s < s1; s++) {
        // prefetch next sample while computing this one
        float4 na, nb, nc;
        if (s + 1 < s1) {
            const float4* n4 = base + (size_t)(s + 1) * F4S;
            na = n4[3 * tid + 0];
            nb = n4[3 * tid + 1];
            nc = n4[3 * tid + 2];
        }

        float S00 = 0, S01 = 0, S02 = 0, S10 = 0, S11 = 0, S12 = 0, S20 = 0, S21 = 0, S22 = 0;
        float P0 = 0, P1 = 0, P2 = 0;
        RES_ACC(w0.w, a.x, a.y, a.z, w0.x, w0.y, w0.z);
        RES_ACC(w1.w, a.w, bq.x, bq.y, w1.x, w1.y, w1.z);
        RES_ACC(w2.w, bq.z, bq.w, c.x, w2.x, w2.y, w2.z);
        RES_ACC(w3.w, c.y, c.z, c.w, w3.x, w3.y, w3.z);

        float vals[12] = {S00, S01, S02, S10, S11, S12, S20, S21, S22, P0, P1, P2};
#pragma unroll
        for (int k = 0; k < 12; k++) {
            float v = warpsum(vals[k]);
            if (lane == 0) red[k][wid] = v;
        }
        __syncthreads();
        if (tid < 12) {
            float v = 0.f;
#pragma unroll
            for (int i = 0; i < 32; i++) v += red[tid][i];
            g_S[s * 12 + tid] = v;
        }
        __syncthreads();   // red reused next iteration

        a = na; bq = nb; c = nc;
    }
}

// ---------------- kernel C: Horn quaternion Kabsch ----------------
__global__ void k_rot() {
    int s = blockIdx.x * blockDim.x + threadIdx.x;
    if (s >= NS) return;

    float Sf[12];
#pragma unroll
    for (int i = 0; i < 12; i++) Sf[i] = g_S[s * 12 + i];
    float Sxx = Sf[0], Sxy = Sf[1], Sxz = Sf[2];
    float Syx = Sf[3], Syy = Sf[4], Syz = Sf[5];
    float Szx = Sf[6], Szy = Sf[7], Szz = Sf[8];

    float A[4][4];
    A[0][0] = Sxx + Syy + Szz; A[0][1] = Syz - Szy;         A[0][2] = Szx - Sxz;         A[0][3] = Sxy - Syx;
    A[1][1] = Sxx - Syy - Szz; A[1][2] = Sxy + Syx;         A[1][3] = Szx + Sxz;
    A[2][2] = -Sxx + Syy - Szz; A[2][3] = Syz + Szy;
    A[3][3] = -Sxx - Syy + Szz;
    A[1][0] = A[0][1]; A[2][0] = A[0][2]; A[3][0] = A[0][3];
    A[2][1] = A[1][2]; A[3][1] = A[1][3]; A[3][2] = A[2][3];

    float V[4][4] = {{1, 0, 0, 0}, {0, 1, 0, 0}, {0, 0, 1, 0}, {0, 0, 0, 1}};

    for (int sweep = 0; sweep < 4; sweep++) {
#pragma unroll
        for (int p = 0; p < 3; p++) {
#pragma unroll
            for (int q = p + 1; q < 4; q++) {
                float apq = A[p][q];
                float scale = fabsf(A[p][p]) + fabsf(A[q][q]);
                if (fabsf(apq) > 1e-12f * scale + 1e-30f) {
                    float theta = (A[q][q] - A[p][p]) / (2.0f * apq);
                    float t = 1.0f / (fabsf(theta) + sqrtf(theta * theta + 1.0f));
                    if (theta < 0.0f) t = -t;
                    float cth = 1.0f / sqrtf(t * t + 1.0f);
                    float sth = t * cth;
#pragma unroll
                    for (int r = 0; r < 4; r++) {
                        float arp = A[r][p], arq = A[r][q];
                        A[r][p] = arp * cth - arq * sth;
                        A[r][q] = arp * sth + arq * cth;
                    }
#pragma unroll
                    for (int r = 0; r < 4; r++) {
                        float apr = A[p][r], aqr = A[q][r];
                        A[p][r] = apr * cth - aqr * sth;
                        A[q][r] = apr * sth + aqr * cth;
                    }
#pragma unroll
                    for (int r = 0; r < 4; r++) {
                        float vrp = V[r][p], vrq = V[r][q];
                        V[r][p] = vrp * cth - vrq * sth;
                        V[r][q] = vrp * sth + vrq * cth;
                    }
                }
            }
        }
    }

    int kk = 0;
    float best = A[0][0];
#pragma unroll
    for (int i = 1; i < 4; i++) if (A[i][i] > best) { best = A[i][i]; kk = i; }
    float q0 = V[0][kk], qx = V[1][kk], qy = V[2][kk], qz = V[3][kk];

    float R[3][3];
    R[0][0] = q0 * q0 + qx * qx - qy * qy - qz * qz;
    R[0][1] = 2.0f * (qx * qy - q0 * qz);
    R[0][2] = 2.0f * (qx * qz + q0 * qy);
    R[1][0] = 2.0f * (qy * qx + q0 * qz);
    R[1][1] = q0 * q0 - qx * qx + qy * qy - qz * qz;
    R[1][2] = 2.0f * (qy * qz - q0 * qx);
    R[2][0] = 2.0f * (qz * qx - q0 * qy);
    R[2][1] = 2.0f * (qz * qy + q0 * qx);
    R[2][2] = q0 * q0 - qx * qx - qy * qy + qz * qz;

    // orientation safeguard
    float Sm[3][3] = {{Sxx, Sxy, Sxz}, {Syx, Syy, Syz}, {Szx, Szy, Szz}};
    float obj = 0.f, objT = 0.f;
#pragma unroll
    for (int i = 0; i < 3; i++)
#pragma unroll
        for (int j = 0; j < 3; j++) {
            obj  += R[i][j] * Sm[j][i];
            objT += R[j][i] * Sm[j][i];
        }
    if (objT > obj) {
#pragma unroll
        for (int i = 0; i < 3; i++)
#pragma unroll
            for (int j = i + 1; j < 3; j++) {
                float tmp = R[i][j]; R[i][j] = R[j][i]; R[j][i] = tmp;
            }
    }

    float invLt = g_stats[4];
    float pm0 = Sf[9] * invLt, pm1 = Sf[10] * invLt, pm2 = Sf[11] * invLt;
    int base = s * 14;
    g_RT[base + 0] = R[0][0]; g_RT[base + 1] = R[0][1]; g_RT[base + 2] = R[0][2];
    g_RT[base + 3] = R[1][0]; g_RT[base + 4] = R[1][1]; g_RT[base + 5] = R[1][2];
    g_RT[base + 6] = R[2][0]; g_RT[base + 7] = R[2][1]; g_RT[base + 8] = R[2][2];
    g_RT[base + 9]  = R[0][0] * pm0 + R[0][1] * pm1 + R[0][2] * pm2;
    g_RT[base + 10] = R[1][0] * pm0 + R[1][1] * pm1 + R[1][2] * pm2;
    g_RT[base + 11] = R[2][0] * pm0 + R[2][1] * pm1 + R[2][2] * pm2;
    g_RT[base + 12] = g_stats[5];
    g_RT[base + 13] = invLt;
}

// ---------------- kernel D: TM score, multi-sample persistent blocks ----------------
#define RES_TM(wv, px, py, pz, tx, ty, tz) do { \
    float dx = fmaf(R00, (px), fmaf(R01, (py), fmaf(R02, (pz), -c0))) - (tx); \
    float dy = fmaf(R10, (px), fmaf(R11, (py), fmaf(R12, (pz), -c1))) - (ty); \
    float dz = fmaf(R20, (px), fmaf(R21, (py), fmaf(R22, (pz), -c2))) - (tz); \
    float dsq = fmaf(dx, dx, fmaf(dy, dy, dz * dz)); \
    acc += (wv) * rcp_fast(fmaf(dsq, invd0, 1.0f)); } while (0)

__global__ void __launch_bounds__(TPB, 1) k_tm(const float* __restrict__ pred,
                                               float* __restrict__ out) {
    int b = blockIdx.x;
    int tid = threadIdx.x;
    int lane = tid & 31, wid = tid >> 5;
    int s0 = (b * NS) / GRID, s1 = ((b + 1) * NS) / GRID;

    __shared__ float red[32];
    __shared__ float P[14];

    float4 w0 = g_wt4[4 * tid + 0];
    float4 w1 = g_wt4[4 * tid + 1];
    float4 w2 = g_wt4[4 * tid + 2];
    float4 w3 = g_wt4[4 * tid + 3];

    const float4* __restrict__ base = reinterpret_cast<const float4*>(pred);
    const float4* p4 = base + (size_t)s0 * F4S;
    float4 a = p4[3 * tid + 0];
    float4 bq = p4[3 * tid + 1];
    float4 c = p4[3 * tid + 2];

    for (int s = s0; s < s1; s++) {
        // prefetch next sample first (loads in flight across barriers)
        float4 na, nb, nc;
        if (s + 1 < s1) {
            const float4* n4 = base + (size_t)(s + 1) * F4S;
            na = n4[3 * tid + 0];
            nb = n4[3 * tid + 1];
            nc = n4[3 * tid + 2];
        }
        if (tid < 14) P[tid] = g_RT[s * 14 + tid];
        __syncthreads();
        float R00 = P[0], R01 = P[1], R02 = P[2];
        float R10 = P[3], R11 = P[4], R12 = P[5];
        float R20 = P[6], R21 = P[7], R22 = P[8];
        float c0 = P[9], c1 = P[10], c2 = P[11];
        float invd0 = P[12], invLt = P[13];

        float acc = 0.f;
        RES_TM(w0.w, a.x, a.y, a.z, w0.x, w0.y, w0.z);
        RES_TM(w1.w, a.w, bq.x, bq.y, w1.x, w1.y, w1.z);
        RES_TM(w2.w, bq.z, bq.w, c.x, w2.x, w2.y, w2.z);
        RES_TM(w3.w, c.y, c.z, c.w, w3.x, w3.y, w3.z);

        acc = warpsum(acc);
        if (lane == 0) red[wid] = acc;
        __syncthreads();
        if (tid == 0) {
            float v = 0.f;
#pragma unroll
            for (int i = 0; i < 32; i++) v += red[i];
            out[s] = v * invLt;
        }
        __syncthreads();   // red + P reused next iteration

        a = na; bq = nb; c = nc;
    }
}

// ---------------- launch ----------------
extern "C" void kernel_launch(void* const* d_in, const int* in_sizes, int n_in,
                              void* d_out, int out_size) {
    const float* pred = (const float*)d_in[0];
    const float* truec = (const float*)d_in[1];
    const int* mask = (const int*)d_in[2];
    float* out = (float*)d_out;

    k_pre<<<1, PRE_T>>>(truec, mask);
    k_cov<<<GRID, TPB>>>(pred);
    k_rot<<<8, 128>>>();
    k_tm<<<GRID, TPB>>>(pred, out);
}

// round 10
// speedup vs baseline: 1.0054x; 1.0054x over previous
#include <cuda_runtime.h>
#include <math.h>

#define NS 1024
#define NR 4096
#define TPB 256
#define NSM 148
#define GRID (4 * NSM)                // 4 blocks per SM, one quarter each
#define QRES 1024                     // residues per quarter
#define QF4 (QRES * 3 / 4)            // 768 pred float4 per quarter
#define F4S (NR * 3 / 4)              // 3072 pred float4 per sample

// ---------------- scratch (static device globals; no allocation) ----------------
__device__ __align__(16) float4 g_wt4[NR];   // (w*t_c0, w*t_c1, w*t_c2, w)
__device__ float g_stats[8];                 // [4]=1/Lt, [5]=1/d0^2
__device__ float g_Spart[NS * 4 * 12];       // per (sample,quarter): S(9), P(3)
__device__ float g_RT[NS * 14];              // per sample: R(9), c(3), invd0, invLt
__device__ float g_tmpart[NS * 4];           // per (sample,quarter) TM partial

__device__ __forceinline__ float warpsum(float v) {
#pragma unroll
    for (int o = 16; o; o >>= 1) v += __shfl_down_sync(0xffffffffu, v, o);
    return v;
}

__device__ __forceinline__ float rcp_fast(float x) {
    float r;
    asm("rcp.approx.f32 %0, %1;" : "=f"(r) : "f"(x));
    return r;
}

// ---------------- kernel A: true stats + wt4 companion ----------------
#define PRE_T 1024
__global__ void k_pre(const float* __restrict__ truec, const int* __restrict__ mask) {
    int tid = threadIdx.x;
    float ws = 0.f, wt0 = 0.f, wt1 = 0.f, wt2 = 0.f;
    for (int l = tid; l < NR; l += PRE_T) {
        float w = (mask[l] != 0) ? 1.0f : 0.0f;
        ws += w;
        wt0 += w * truec[l * 3 + 0];
        wt1 += w * truec[l * 3 + 1];
        wt2 += w * truec[l * 3 + 2];
    }
    __shared__ float sm[4][32];
    __shared__ float s_tm[3];
    int lane = tid & 31, wid = tid >> 5;
    ws = warpsum(ws); wt0 = warpsum(wt0); wt1 = warpsum(wt1); wt2 = warpsum(wt2);
    if (lane == 0) { sm[0][wid] = ws; sm[1][wid] = wt0; sm[2][wid] = wt1; sm[3][wid] = wt2; }
    __syncthreads();
    if (tid == 0) {
        float Lt = 0.f, a = 0.f, b = 0.f, c = 0.f;
        for (int i = 0; i < 32; i++) { Lt += sm[0][i]; a += sm[1][i]; b += sm[2][i]; c += sm[3][i]; }
        float inv = 1.0f / Lt;
        float m0 = a * inv, m1 = b * inv, m2 = c * inv;
        float d0 = (Lt <= 15.0f) ? 0.5f : (1.24f * cbrtf(Lt - 15.0f) - 1.8f);
        d0 = fmaxf(d0, 0.5f);
        g_stats[0] = m0; g_stats[1] = m1; g_stats[2] = m2;
        g_stats[3] = Lt; g_stats[4] = inv; g_stats[5] = 1.0f / (d0 * d0);
        s_tm[0] = m0; s_tm[1] = m1; s_tm[2] = m2;
    }
    __syncthreads();
    float m0 = s_tm[0], m1 = s_tm[1], m2 = s_tm[2];
    for (int l = tid; l < NR; l += PRE_T) {
        float w = (mask[l] != 0) ? 1.0f : 0.0f;
        float4 v;
        v.x = w * (truec[l * 3 + 0] - m0);
        v.y = w * (truec[l * 3 + 1] - m1);
        v.z = w * (truec[l * 3 + 2] - m2);
        v.w = w;
        g_wt4[l] = v;
    }
}

// ---------------- kernel B: covariance, quarter-persistent blocks ----------------
#define RES_ACC(wv, px, py, pz, tx, ty, tz) do { \
    S00 = fmaf((px), (tx), S00); S01 = fmaf((px), (ty), S01); S02 = fmaf((px), (tz), S02); \
    S10 = fmaf((py), (tx), S10); S11 = fmaf((py), (ty), S11); S12 = fmaf((py), (tz), S12); \
    S20 = fmaf((pz), (tx), S20); S21 = fmaf((pz), (ty), S21); S22 = fmaf((pz), (tz), S22); \
    P0 = fmaf((wv), (px), P0); P1 = fmaf((wv), (py), P1); P2 = fmaf((wv), (pz), P2); } while (0)

__global__ void __launch_bounds__(TPB, 4) k_cov(const float* __restrict__ pred) {
    int b = blockIdx.x;
    int q = b & 3, sid0 = b >> 2;          // quarter + first sample
    int tid = threadIdx.x;
    int lane = tid & 31, wid = tid >> 5;

    __shared__ float red[12][8];

    // companions for this quarter: loaded ONCE per block lifetime
    const float4* __restrict__ wq = g_wt4 + q * QRES;
    float4 w0 = wq[4 * tid + 0];
    float4 w1 = wq[4 * tid + 1];
    float4 w2 = wq[4 * tid + 2];
    float4 w3 = wq[4 * tid + 3];

    const float4* __restrict__ base = reinterpret_cast<const float4*>(pred) + q * QF4;

    int s = sid0;
    const float4* p4 = base + (size_t)s * F4S;
    float4 a = p4[3 * tid + 0];
    float4 bq = p4[3 * tid + 1];
    float4 c = p4[3 * tid + 2];

    while (s < NS) {
        int sn = s + NSM;
        float4 na, nb, nc;
        if (sn < NS) {
            const float4* n4 = base + (size_t)sn * F4S;
            na = n4[3 * tid + 0];
            nb = n4[3 * tid + 1];
            nc = n4[3 * tid + 2];
        }

        float S00 = 0, S01 = 0, S02 = 0, S10 = 0, S11 = 0, S12 = 0, S20 = 0, S21 = 0, S22 = 0;
        float P0 = 0, P1 = 0, P2 = 0;
        RES_ACC(w0.w, a.x, a.y, a.z, w0.x, w0.y, w0.z);
        RES_ACC(w1.w, a.w, bq.x, bq.y, w1.x, w1.y, w1.z);
        RES_ACC(w2.w, bq.z, bq.w, c.x, w2.x, w2.y, w2.z);
        RES_ACC(w3.w, c.y, c.z, c.w, w3.x, w3.y, w3.z);

        float vals[12] = {S00, S01, S02, S10, S11, S12, S20, S21, S22, P0, P1, P2};
#pragma unroll
        for (int k = 0; k < 12; k++) {
            float v = warpsum(vals[k]);
            if (lane == 0) red[k][wid] = v;
        }
        __syncthreads();
        if (tid < 12) {
            float v = 0.f;
#pragma unroll
            for (int i = 0; i < 8; i++) v += red[tid][i];
            g_Spart[(s * 4 + q) * 12 + tid] = v;
        }
        __syncthreads();

        a = na; bq = nb; c = nc;
        s = sn;
    }
}

// ---------------- kernel C: reduce quarters + Horn quaternion Kabsch ----------------
__global__ void k_rot() {
    int s = blockIdx.x * blockDim.x + threadIdx.x;
    if (s >= NS) return;

    float Sf[12];
#pragma unroll
    for (int i = 0; i < 12; i++) {
        float v = 0.f;
#pragma unroll
        for (int j = 0; j < 4; j++) v += g_Spart[(s * 4 + j) * 12 + i];
        Sf[i] = v;
    }
    float Sxx = Sf[0], Sxy = Sf[1], Sxz = Sf[2];
    float Syx = Sf[3], Syy = Sf[4], Syz = Sf[5];
    float Szx = Sf[6], Szy = Sf[7], Szz = Sf[8];

    float A[4][4];
    A[0][0] = Sxx + Syy + Szz; A[0][1] = Syz - Szy;         A[0][2] = Szx - Sxz;         A[0][3] = Sxy - Syx;
    A[1][1] = Sxx - Syy - Szz; A[1][2] = Sxy + Syx;         A[1][3] = Szx + Sxz;
    A[2][2] = -Sxx + Syy - Szz; A[2][3] = Syz + Szy;
    A[3][3] = -Sxx - Syy + Szz;
    A[1][0] = A[0][1]; A[2][0] = A[0][2]; A[3][0] = A[0][3];
    A[2][1] = A[1][2]; A[3][1] = A[1][3]; A[3][2] = A[2][3];

    float V[4][4] = {{1, 0, 0, 0}, {0, 1, 0, 0}, {0, 0, 1, 0}, {0, 0, 0, 1}};

    for (int sweep = 0; sweep < 4; sweep++) {
#pragma unroll
        for (int p = 0; p < 3; p++) {
#pragma unroll
            for (int q = p + 1; q < 4; q++) {
                float apq = A[p][q];
                float scale = fabsf(A[p][p]) + fabsf(A[q][q]);
                if (fabsf(apq) > 1e-12f * scale + 1e-30f) {
                    float theta = (A[q][q] - A[p][p]) / (2.0f * apq);
                    float t = 1.0f / (fabsf(theta) + sqrtf(theta * theta + 1.0f));
                    if (theta < 0.0f) t = -t;
                    float cth = 1.0f / sqrtf(t * t + 1.0f);
                    float sth = t * cth;
#pragma unroll
                    for (int r = 0; r < 4; r++) {
                        float arp = A[r][p], arq = A[r][q];
                        A[r][p] = arp * cth - arq * sth;
                        A[r][q] = arp * sth + arq * cth;
                    }
#pragma unroll
                    for (int r = 0; r < 4; r++) {
                        float apr = A[p][r], aqr = A[q][r];
                        A[p][r] = apr * cth - aqr * sth;
                        A[q][r] = apr * sth + aqr * cth;
                    }
#pragma unroll
                    for (int r = 0; r < 4; r++) {
                        float vrp = V[r][p], vrq = V[r][q];
                        V[r][p] = vrp * cth - vrq * sth;
                        V[r][q] = vrp * sth + vrq * cth;
                    }
                }
            }
        }
    }

    int kk = 0;
    float best = A[0][0];
#pragma unroll
    for (int i = 1; i < 4; i++) if (A[i][i] > best) { best = A[i][i]; kk = i; }
    float q0 = V[0][kk], qx = V[1][kk], qy = V[2][kk], qz = V[3][kk];

    float R[3][3];
    R[0][0] = q0 * q0 + qx * qx - qy * qy - qz * qz;
    R[0][1] = 2.0f * (qx * qy - q0 * qz);
    R[0][2] = 2.0f * (qx * qz + q0 * qy);
    R[1][0] = 2.0f * (qy * qx + q0 * qz);
    R[1][1] = q0 * q0 - qx * qx + qy * qy - qz * qz;
    R[1][2] = 2.0f * (qy * qz - q0 * qx);
    R[2][0] = 2.0f * (qz * qx - q0 * qy);
    R[2][1] = 2.0f * (qz * qy + q0 * qx);
    R[2][2] = q0 * q0 - qx * qx - qy * qy + qz * qz;

    // orientation safeguard
    float Sm[3][3] = {{Sxx, Sxy, Sxz}, {Syx, Syy, Syz}, {Szx, Szy, Szz}};
    float obj = 0.f, objT = 0.f;
#pragma unroll
    for (int i = 0; i < 3; i++)
#pragma unroll
        for (int j = 0; j < 3; j++) {
            obj  += R[i][j] * Sm[j][i];
            objT += R[j][i] * Sm[j][i];
        }
    if (objT > obj) {
#pragma unroll
        for (int i = 0; i < 3; i++)
#pragma unroll
            for (int j = i + 1; j < 3; j++) {
                float tmp = R[i][j]; R[i][j] = R[j][i]; R[j][i] = tmp;
            }
    }

    float invLt = g_stats[4];
    float pm0 = Sf[9] * invLt, pm1 = Sf[10] * invLt, pm2 = Sf[11] * invLt;
    int base = s * 14;
    g_RT[base + 0] = R[0][0]; g_RT[base + 1] = R[0][1]; g_RT[base + 2] = R[0][2];
    g_RT[base + 3] = R[1][0]; g_RT[base + 4] = R[1][1]; g_RT[base + 5] = R[1][2];
    g_RT[base + 6] = R[2][0]; g_RT[base + 7] = R[2][1]; g_RT[base + 8] = R[2][2];
    g_RT[base + 9]  = R[0][0] * pm0 + R[0][1] * pm1 + R[0][2] * pm2;
    g_RT[base + 10] = R[1][0] * pm0 + R[1][1] * pm1 + R[1][2] * pm2;
    g_RT[base + 11] = R[2][0] * pm0 + R[2][1] * pm1 + R[2][2] * pm2;
    g_RT[base + 12] = g_stats[5];
    g_RT[base + 13] = invLt;
}

// ---------------- kernel D: TM partials, quarter-persistent blocks ----------------
#define RES_TM(wv, px, py, pz, tx, ty, tz) do { \
    float dx = fmaf(R00, (px), fmaf(R01, (py), fmaf(R02, (pz), -c0))) - (tx); \
    float dy = fmaf(R10, (px), fmaf(R11, (py), fmaf(R12, (pz), -c1))) - (ty); \
    float dz = fmaf(R20, (px), fmaf(R21, (py), fmaf(R22, (pz), -c2))) - (tz); \
    float dsq = fmaf(dx, dx, fmaf(dy, dy, dz * dz)); \
    acc += (wv) * rcp_fast(fmaf(dsq, invd0, 1.0f)); } while (0)

__global__ void __launch_bounds__(TPB, 4) k_tm(const float* __restrict__ pred) {
    int b = blockIdx.x;
    int q = b & 3, sid0 = b >> 2;
    int tid = threadIdx.x;
    int lane = tid & 31, wid = tid >> 5;

    __shared__ float red[8];
    __shared__ float P[14];

    const float4* __restrict__ wq = g_wt4 + q * QRES;
    float4 w0 = wq[4 * tid + 0];
    float4 w1 = wq[4 * tid + 1];
    float4 w2 = wq[4 * tid + 2];
    float4 w3 = wq[4 * tid + 3];

    const float4* __restrict__ base = reinterpret_cast<const float4*>(pred) + q * QF4;

    int s = sid0;
    const float4* p4 = base + (size_t)s * F4S;
    float4 a = p4[3 * tid + 0];
    float4 bq = p4[3 * tid + 1];
    float4 c = p4[3 * tid + 2];

    while (s < NS) {
        int sn = s + NSM;
        float4 na, nb, nc;
        if (sn < NS) {
            const float4* n4 = base + (size_t)sn * F4S;
            na = n4[3 * tid + 0];
            nb = n4[3 * tid + 1];
            nc = n4[3 * tid + 2];
        }
        if (tid < 14) P[tid] = g_RT[s * 14 + tid];
        __syncthreads();
        float R00 = P[0], R01 = P[1], R02 = P[2];
        float R10 = P[3], R11 = P[4], R12 = P[5];
        float R20 = P[6], R21 = P[7], R22 = P[8];
        float c0 = P[9], c1 = P[10], c2 = P[11];
        float invd0 = P[12];

        float acc = 0.f;
        RES_TM(w0.w, a.x, a.y, a.z, w0.x, w0.y, w0.z);
        RES_TM(w1.w, a.w, bq.x, bq.y, w1.x, w1.y, w1.z);
        RES_TM(w2.w, bq.z, bq.w, c.x, w2.x, w2.y, w2.z);
        RES_TM(w3.w, c.y, c.z, c.w, w3.x, w3.y, w3.z);

        acc = warpsum(acc);
        if (lane == 0) red[wid] = acc;
        __syncthreads();
        if (tid == 0) {
            float v = 0.f;
#pragma unroll
            for (int i = 0; i < 8; i++) v += red[i];
            g_tmpart[s * 4 + q] = v;
        }
        __syncthreads();

        a = na; bq = nb; c = nc;
        s = sn;
    }
}

// ---------------- kernel E: final reduction ----------------
__global__ void k_final(float* __restrict__ out) {
    int s = blockIdx.x * blockDim.x + threadIdx.x;
    if (s >= NS) return;
    float invLt = g_stats[4];
    float v = g_tmpart[s * 4 + 0] + g_tmpart[s * 4 + 1]
            + g_tmpart[s * 4 + 2] + g_tmpart[s * 4 + 3];
    out[s] = v * invLt;
}

// ---------------- launch ----------------
extern "C" void kernel_launch(void* const* d_in, const int* in_sizes, int n_in,
                              void* d_out, int out_size) {
    const float* pred = (const float*)d_in[0];
    const float* truec = (const float*)d_in[1];
    const int* mask = (const int*)d_in[2];
    float* out = (float*)d_out;

    k_pre<<<1, PRE_T>>>(truec, mask);
    k_cov<<<GRID, TPB>>>(pred);
    k_rot<<<8, 128>>>();
    k_tm<<<GRID, TPB>>>(pred);
    k_final<<<4, 256>>>(out);
}

// round 13
// speedup vs baseline: 1.1813x; 1.1750x over previous
#include <cuda_runtime.h>
#include <math.h>

#define NS 1024
#define NR 4096
#define NSM 148
#define GRIDP (2 * NSM)   // 296 blocks, exactly 2 per SM
#define TPB 256

// ---------------- scratch (static device globals; no allocation) ----------------
__device__ float g_Spart[NS * 2 * 12];   // per (sample, half): S(9), P(3)
__device__ float g_RT[NS * 12];          // per sample: R(9), c(3)
__device__ float g_tmpart[NS * 2];       // per (sample, half) TM partial
__device__ unsigned g_barA = 0, g_barG = 0;

__device__ __forceinline__ float warpsum(float v) {
#pragma unroll
    for (int o = 16; o; o >>= 1) v += __shfl_down_sync(0xffffffffu, v, o);
    return v;
}

__device__ __forceinline__ float rcp_fast(float x) {
    float r;
    asm("rcp.approx.f32 %0, %1;" : "=f"(r) : "f"(x));
    return r;
}

// sense-reversing grid barrier; safe because all GRIDP blocks are co-resident
__device__ __forceinline__ void grid_barrier() {
    __threadfence();
    __syncthreads();
    if (threadIdx.x == 0) {
        unsigned gen = atomicAdd(&g_barG, 0u);
        unsigned t = atomicAdd(&g_barA, 1u);
        if (t == GRIDP - 1) {
            atomicExch(&g_barA, 0u);
            __threadfence();
            atomicAdd(&g_barG, 1u);
        } else {
            while (atomicAdd(&g_barG, 0u) == gen) __nanosleep(64);
        }
    }
    __syncthreads();
}

// residue packing within a float4-triple (A,B,C) = 4 residues:
// r0=(A.x,A.y,A.z) r1=(A.w,B.x,B.y) r2=(B.z,B.w,C.x) r3=(C.y,C.z,C.w)

__global__ void __launch_bounds__(TPB, 2) k_all(const float* __restrict__ pred,
                                                const float* __restrict__ truec,
                                                const int* __restrict__ mask,
                                                float* __restrict__ out) {
    int b = blockIdx.x;
    int col = b >> 1, h = b & 1;
    int tid = threadIdx.x;
    int lane = tid & 31, wid = tid >> 5;

    __shared__ float red[12][8];
    __shared__ float bc[6];     // m0 m1 m2 invLt invd0
    __shared__ float Psh[12];   // R(9), c(3) per sample

    // ================= phase 1: stats (redundant) + own-group capture ========
    const float4* __restrict__ t4 = reinterpret_cast<const float4*>(truec);
    const int4* __restrict__ m4 = reinterpret_cast<const int4*>(mask);

    float ws = 0.f, wt0 = 0.f, wt1 = 0.f, wt2 = 0.f;
    float4 oA0, oB0, oC0, oA1, oB1, oC1;
    int4 oM0, oM1;
#pragma unroll
    for (int k = 0; k < 4; k++) {
        int g = tid + k * 256;
        float4 A = t4[3 * g], B = t4[3 * g + 1], C = t4[3 * g + 2];
        int4 M = m4[g];
        float w0 = M.x ? 1.f : 0.f, w1 = M.y ? 1.f : 0.f;
        float w2 = M.z ? 1.f : 0.f, w3 = M.w ? 1.f : 0.f;
        ws += w0 + w1 + w2 + w3;
        wt0 += w0 * A.x + w1 * A.w + w2 * B.z + w3 * C.y;
        wt1 += w0 * A.y + w1 * B.x + w2 * B.w + w3 * C.z;
        wt2 += w0 * A.z + w1 * B.y + w2 * C.x + w3 * C.w;
        if (k == 2 * h)     { oA0 = A; oB0 = B; oC0 = C; oM0 = M; }
        if (k == 2 * h + 1) { oA1 = A; oB1 = B; oC1 = C; oM1 = M; }
    }
    {
        float vals[4] = {ws, wt0, wt1, wt2};
#pragma unroll
        for (int k = 0; k < 4; k++) {
            float v = warpsum(vals[k]);
            if (lane == 0) red[k][wid] = v;
        }
    }
    __syncthreads();
    if (tid == 0) {
        float Lt = 0.f, a = 0.f, bb = 0.f, c = 0.f;
#pragma unroll
        for (int i = 0; i < 8; i++) { Lt += red[0][i]; a += red[1][i]; bb += red[2][i]; c += red[3][i]; }
        float inv = 1.0f / Lt;
        float d0 = (Lt <= 15.0f) ? 0.5f : (1.24f * cbrtf(Lt - 15.0f) - 1.8f);
        d0 = fmaxf(d0, 0.5f);
        bc[0] = a * inv; bc[1] = bb * inv; bc[2] = c * inv;
        bc[3] = inv; bc[4] = 1.0f / (d0 * d0);
    }
    __syncthreads();
    float m0 = bc[0], m1 = bc[1], m2 = bc[2], invLt = bc[3], invd0 = bc[4];

    // companions in registers: w[8], wtc{x,y,z}[8] = w*(t - m)
    float W[8], TX[8], TY[8], TZ[8];
    W[0] = oM0.x ? 1.f : 0.f; TX[0] = W[0]*(oA0.x-m0); TY[0] = W[0]*(oA0.y-m1); TZ[0] = W[0]*(oA0.z-m2);
    W[1] = oM0.y ? 1.f : 0.f; TX[1] = W[1]*(oA0.w-m0); TY[1] = W[1]*(oB0.x-m1); TZ[1] = W[1]*(oB0.y-m2);
    W[2] = oM0.z ? 1.f : 0.f; TX[2] = W[2]*(oB0.z-m0); TY[2] = W[2]*(oB0.w-m1); TZ[2] = W[2]*(oC0.x-m2);
    W[3] = oM0.w ? 1.f : 0.f; TX[3] = W[3]*(oC0.y-m0); TY[3] = W[3]*(oC0.z-m1); TZ[3] = W[3]*(oC0.w-m2);
    W[4] = oM1.x ? 1.f : 0.f; TX[4] = W[4]*(oA1.x-m0); TY[4] = W[4]*(oA1.y-m1); TZ[4] = W[4]*(oA1.z-m2);
    W[5] = oM1.y ? 1.f : 0.f; TX[5] = W[5]*(oA1.w-m0); TY[5] = W[5]*(oB1.x-m1); TZ[5] = W[5]*(oB1.y-m2);
    W[6] = oM1.z ? 1.f : 0.f; TX[6] = W[6]*(oB1.z-m0); TY[6] = W[6]*(oB1.w-m1); TZ[6] = W[6]*(oC1.x-m2);
    W[7] = oM1.w ? 1.f : 0.f; TX[7] = W[7]*(oC1.y-m0); TY[7] = W[7]*(oC1.z-m1); TZ[7] = W[7]*(oC1.w-m2);

    const float4* __restrict__ p4 = reinterpret_cast<const float4*>(pred);
    size_t hoff = (size_t)h * 1536;
    int nsamp = (col < 136) ? 7 : 6;

#define LOADP(s_, A0_, B0_, C0_, A1_, B1_, C1_) do { \
    const float4* pp = p4 + (size_t)(s_) * 3072 + hoff; \
    A0_ = pp[3 * tid]; B0_ = pp[3 * tid + 1]; C0_ = pp[3 * tid + 2]; \
    A1_ = pp[3 * (tid + 256)]; B1_ = pp[3 * (tid + 256) + 1]; C1_ = pp[3 * (tid + 256) + 2]; } while (0)

    // ================= phase 2: covariance loop ==============================
    {
        float4 a0, b0, c0, a1, b1, c1;
        int s = col;
        LOADP(s, a0, b0, c0, a1, b1, c1);
        while (s < NS) {
            int sn = s + NSM;
            float4 na0, nb0, nc0, na1, nb1, nc1;
            if (sn < NS) LOADP(sn, na0, nb0, nc0, na1, nb1, nc1);

            float S00=0,S01=0,S02=0,S10=0,S11=0,S12=0,S20=0,S21=0,S22=0,P0=0,P1=0,P2=0;
#define CACC(i, px, py, pz) do { \
    S00 = fmaf((px), TX[i], S00); S01 = fmaf((px), TY[i], S01); S02 = fmaf((px), TZ[i], S02); \
    S10 = fmaf((py), TX[i], S10); S11 = fmaf((py), TY[i], S11); S12 = fmaf((py), TZ[i], S12); \
    S20 = fmaf((pz), TX[i], S20); S21 = fmaf((pz), TY[i], S21); S22 = fmaf((pz), TZ[i], S22); \
    P0 = fmaf(W[i], (px), P0); P1 = fmaf(W[i], (py), P1); P2 = fmaf(W[i], (pz), P2); } while (0)
            CACC(0, a0.x, a0.y, a0.z); CACC(1, a0.w, b0.x, b0.y);
            CACC(2, b0.z, b0.w, c0.x); CACC(3, c0.y, c0.z, c0.w);
            CACC(4, a1.x, a1.y, a1.z); CACC(5, a1.w, b1.x, b1.y);
            CACC(6, b1.z, b1.w, c1.x); CACC(7, c1.y, c1.z, c1.w);

            float vals[12] = {S00,S01,S02,S10,S11,S12,S20,S21,S22,P0,P1,P2};
#pragma unroll
            for (int k = 0; k < 12; k++) {
                float v = warpsum(vals[k]);
                if (lane == 0) red[k][wid] = v;
            }
            __syncthreads();
            if (tid < 12) {
                float v = 0.f;
#pragma unroll
                for (int i = 0; i < 8; i++) v += red[tid][i];
                g_Spart[(s * 2 + h) * 12 + tid] = v;
            }
            __syncthreads();
            a0 = na0; b0 = nb0; c0 = nc0; a1 = na1; b1 = nb1; c1 = nc1;
            s = sn;
        }
    }
    grid_barrier();

    // ================= phase 3: rotations (half-0 blocks, 1 thread/sample) ===
    if (h == 0 && tid < nsamp) {
        int s = col + NSM * tid;
        float Sf[12];
#pragma unroll
        for (int i = 0; i < 12; i++)
            Sf[i] = __ldcg(&g_Spart[(s * 2) * 12 + i]) + __ldcg(&g_Spart[(s * 2 + 1) * 12 + i]);
        float Sxx = Sf[0], Sxy = Sf[1], Sxz = Sf[2];
        float Syx = Sf[3], Syy = Sf[4], Syz = Sf[5];
        float Szx = Sf[6], Szy = Sf[7], Szz = Sf[8];

        float A[4][4];
        A[0][0] = Sxx + Syy + Szz; A[0][1] = Syz - Szy;          A[0][2] = Szx - Sxz;          A[0][3] = Sxy - Syx;
        A[1][1] = Sxx - Syy - Szz; A[1][2] = Sxy + Syx;          A[1][3] = Szx + Sxz;
        A[2][2] = -Sxx + Syy - Szz; A[2][3] = Syz + Szy;
        A[3][3] = -Sxx - Syy + Szz;
        A[1][0] = A[0][1]; A[2][0] = A[0][2]; A[3][0] = A[0][3];
        A[2][1] = A[1][2]; A[3][1] = A[1][3]; A[3][2] = A[2][3];
        float V[4][4] = {{1,0,0,0},{0,1,0,0},{0,0,1,0},{0,0,0,1}};

        for (int sweep = 0; sweep < 4; sweep++) {
#pragma unroll
            for (int p = 0; p < 3; p++) {
#pragma unroll
                for (int q = p + 1; q < 4; q++) {
                    float apq = A[p][q];
                    float scale = fabsf(A[p][p]) + fabsf(A[q][q]);
                    if (fabsf(apq) > 1e-12f * scale + 1e-30f) {
                        float theta = (A[q][q] - A[p][p]) / (2.0f * apq);
                        float t = 1.0f / (fabsf(theta) + sqrtf(theta * theta + 1.0f));
                        if (theta < 0.0f) t = -t;
                        float cth = 1.0f / sqrtf(t * t + 1.0f);
                        float sth = t * cth;
#pragma unroll
                        for (int r = 0; r < 4; r++) {
                            float arp = A[r][p], arq = A[r][q];
                            A[r][p] = arp * cth - arq * sth;
                            A[r][q] = arp * sth + arq * cth;
                        }
#pragma unroll
                        for (int r = 0; r < 4; r++) {
                            float apr = A[p][r], aqr = A[q][r];
                            A[p][r] = apr * cth - aqr * sth;
                            A[q][r] = apr * sth + aqr * cth;
                        }
#pragma unroll
                        for (int r = 0; r < 4; r++) {
                            float vrp = V[r][p], vrq = V[r][q];
                            V[r][p] = vrp * cth - vrq * sth;
                            V[r][q] = vrp * sth + vrq * cth;
                        }
                    }
                }
            }
        }

        int kk = 0;
        float best = A[0][0];
#pragma unroll
        for (int i = 1; i < 4; i++) if (A[i][i] > best) { best = A[i][i]; kk = i; }
        float q0 = V[0][kk], qx = V[1][kk], qy = V[2][kk], qz = V[3][kk];

        float R[3][3];
        R[0][0] = q0*q0 + qx*qx - qy*qy - qz*qz;
        R[0][1] = 2.0f * (qx*qy - q0*qz);
        R[0][2] = 2.0f * (qx*qz + q0*qy);
        R[1][0] = 2.0f * (qy*qx + q0*qz);
        R[1][1] = q0*q0 - qx*qx + qy*qy - qz*qz;
        R[1][2] = 2.0f * (qy*qz - q0*qx);
        R[2][0] = 2.0f * (qz*qx - q0*qy);
        R[2][1] = 2.0f * (qz*qy + q0*qx);
        R[2][2] = q0*q0 - qx*qx - qy*qy + qz*qz;

        float Sm[3][3] = {{Sxx,Sxy,Sxz},{Syx,Syy,Syz},{Szx,Szy,Szz}};
        float obj = 0.f, objT = 0.f;
#pragma unroll
        for (int i = 0; i < 3; i++)
#pragma unroll
            for (int j = 0; j < 3; j++) {
                obj  += R[i][j] * Sm[j][i];
                objT += R[j][i] * Sm[j][i];
            }
        if (objT > obj) {
#pragma unroll
            for (int i = 0; i < 3; i++)
#pragma unroll
                for (int j = i + 1; j < 3; j++) {
                    float tmp = R[i][j]; R[i][j] = R[j][i]; R[j][i] = tmp;
                }
        }

        float pm0 = Sf[9] * invLt, pm1 = Sf[10] * invLt, pm2 = Sf[11] * invLt;
        int base = s * 12;
        g_RT[base + 0] = R[0][0]; g_RT[base + 1] = R[0][1]; g_RT[base + 2] = R[0][2];
        g_RT[base + 3] = R[1][0]; g_RT[base + 4] = R[1][1]; g_RT[base + 5] = R[1][2];
        g_RT[base + 6] = R[2][0]; g_RT[base + 7] = R[2][1]; g_RT[base + 8] = R[2][2];
        g_RT[base + 9]  = R[0][0]*pm0 + R[0][1]*pm1 + R[0][2]*pm2;
        g_RT[base + 10] = R[1][0]*pm0 + R[1][1]*pm1 + R[1][2]*pm2;
        g_RT[base + 11] = R[2][0]*pm0 + R[2][1]*pm1 + R[2][2]*pm2;
    }
    grid_barrier();

    // ================= phase 4: TM loop ======================================
    {
        float4 a0, b0, c0, a1, b1, c1;
        int s = col;
        LOADP(s, a0, b0, c0, a1, b1, c1);
        while (s < NS) {
            int sn = s + NSM;
            float4 na0, nb0, nc0, na1, nb1, nc1;
            if (sn < NS) LOADP(sn, na0, nb0, nc0, na1, nb1, nc1);
            if (tid < 12) Psh[tid] = __ldcg(&g_RT[s * 12 + tid]);
            __syncthreads();
            float R00 = Psh[0], R01 = Psh[1], R02 = Psh[2];
            float R10 = Psh[3], R11 = Psh[4], R12 = Psh[5];
            float R20 = Psh[6], R21 = Psh[7], R22 = Psh[8];
            float cc0 = Psh[9], cc1 = Psh[10], cc2 = Psh[11];

            float acc = 0.f;
#define TACC(i, px, py, pz) do { \
    float dx = fmaf(R00, (px), fmaf(R01, (py), fmaf(R02, (pz), -cc0))) - TX[i]; \
    float dy = fmaf(R10, (px), fmaf(R11, (py), fmaf(R12, (pz), -cc1))) - TY[i]; \
    float dz = fmaf(R20, (px), fmaf(R21, (py), fmaf(R22, (pz), -cc2))) - TZ[i]; \
    float dsq = fmaf(dx, dx, fmaf(dy, dy, dz * dz)); \
    acc += W[i] * rcp_fast(fmaf(dsq, invd0, 1.0f)); } while (0)
            TACC(0, a0.x, a0.y, a0.z); TACC(1, a0.w, b0.x, b0.y);
            TACC(2, b0.z, b0.w, c0.x); TACC(3, c0.y, c0.z, c0.w);
            TACC(4, a1.x, a1.y, a1.z); TACC(5, a1.w, b1.x, b1.y);
            TACC(6, b1.z, b1.w, c1.x); TACC(7, c1.y, c1.z, c1.w);

            acc = warpsum(acc);
            if (lane == 0) red[0][wid] = acc;
            __syncthreads();
            if (tid == 0) {
                float v = 0.f;
#pragma unroll
                for (int i = 0; i < 8; i++) v += red[0][i];
                g_tmpart[s * 2 + h] = v;
            }
            __syncthreads();
            a0 = na0; b0 = nb0; c0 = nc0; a1 = na1; b1 = nb1; c1 = nc1;
            s = sn;
        }
    }
    grid_barrier();

    // ================= phase 5: output =======================================
    if (h == 0 && tid < nsamp) {
        int s = col + NSM * tid;
        out[s] = (__ldcg(&g_tmpart[2 * s]) + __ldcg(&g_tmpart[2 * s + 1])) * invLt;
    }
}

// ---------------- launch ----------------
extern "C" void kernel_launch(void* const* d_in, const int* in_sizes, int n_in,
                              void* d_out, int out_size) {
    const float* pred = (const float*)d_in[0];
    const float* truec = (const float*)d_in[1];
    const int* mask = (const int*)d_in[2];
    float* out = (float*)d_out;

    k_all<<<GRIDP, TPB>>>(pred, truec, mask, out);
}